// round 3
// baseline (speedup 1.0000x reference)
#include <cuda_runtime.h>

#define N_NODES 50000
#define N_EDGES 800000
#define DIN 128
#define DHID 128
#define NH 8
#define DK 16
#define TN 8
#define TE 8
#define NB 4
#define NCHUNK ((N_NODES + 1023) / 1024)

// ---------------- scratch (static device memory; no allocations) ----------------
__device__ float g_W[4 * TN * DIN * DHID];            // Wk,Wq,Wv,Wa  [4][8][128*128]
__device__ float g_kqv[3 * NH * N_NODES * DK];        // k,q,v in [mat][h][n][16] layout
__device__ float g_vt[(size_t)TE * N_NODES * NH * DK]; // v@msg, [et][n][h][16]  204.8 MB
__device__ float g_elog[(size_t)NH * N_EDGES];        // exp(e-m) [h][p] (sorted edge order)
__device__ float g_dinv[N_NODES * NH];                // 1/denominator per (dst,h)
__device__ float g_agg[N_NODES * DHID];               // aggregated messages [n][128]
__device__ int   g_deg[N_NODES];
__device__ int   g_rowstart[N_NODES + 1];
__device__ int   g_cursor[N_NODES];
__device__ int   g_eidx[N_EDGES];                     // (et<<16)|src, sorted by dst
__device__ int   g_node_order[N_NODES];
__device__ int   g_ncount[TN];
__device__ int   g_tstart[TN + 1];
__device__ int   g_tcur[TN];
__device__ int   g_part[NCHUNK];
__device__ int   g_chunkoff[NCHUNK];

// ---------------- init: zero counters ----------------
__global__ void k_init() {
    int i = blockIdx.x * blockDim.x + threadIdx.x;
    if (i < N_NODES) g_deg[i] = 0;
    if (i < TN) g_ncount[i] = 0;
}

// ---------------- build per-type weight matrices W[t] = comp[t] @ basis ----------------
__global__ void k_prepW(const float* __restrict__ ck, const float* __restrict__ bk,
                        const float* __restrict__ cq, const float* __restrict__ bq,
                        const float* __restrict__ cv, const float* __restrict__ bv,
                        const float* __restrict__ ca, const float* __restrict__ ba) {
    int idx = blockIdx.x * blockDim.x + threadIdx.x;           // 4 * 8 * 16384
    if (idx >= 4 * TN * DIN * DHID) return;
    int m  = idx >> 17;           // matrix id
    int r  = idx & 131071;
    int t  = r >> 14;             // type
    int io = r & 16383;
    const float* comp;
    const float* basis;
    if (m == 0)      { comp = ck; basis = bk; }
    else if (m == 1) { comp = cq; basis = bq; }
    else if (m == 2) { comp = cv; basis = bv; }
    else             { comp = ca; basis = ba; }
    float acc = 0.f;
#pragma unroll
    for (int b = 0; b < NB; b++)
        acc += comp[t * NB + b] * basis[b * (DIN * DHID) + io];
    g_W[idx] = acc;
}

// ---------------- counts: node types + in-degrees ----------------
__global__ void k_count(const int* __restrict__ ntype, const int* __restrict__ dst) {
    int i = blockIdx.x * blockDim.x + threadIdx.x;
    if (i < N_NODES) atomicAdd(&g_ncount[ntype[i]], 1);
    if (i < N_EDGES) atomicAdd(&g_deg[dst[i]], 1);
}

// ---------------- parallel scan phase A: per-chunk exclusive scan + chunk totals ----------------
__global__ void k_scanA() {
    __shared__ int wsum[32];
    int tid = threadIdx.x;
    int chunk = blockIdx.x;
    int i = chunk * 1024 + tid;
    int v = (i < N_NODES) ? g_deg[i] : 0;
    int lane = tid & 31, w = tid >> 5;
    int s = v;
#pragma unroll
    for (int o = 1; o < 32; o <<= 1) {
        int t = __shfl_up_sync(0xffffffffu, s, o);
        if (lane >= o) s += t;
    }
    if (lane == 31) wsum[w] = s;
    __syncthreads();
    if (w == 0) {
        int x = wsum[lane];
#pragma unroll
        for (int o = 1; o < 32; o <<= 1) {
            int t = __shfl_up_sync(0xffffffffu, x, o);
            if (lane >= o) x += t;
        }
        wsum[lane] = x;
    }
    __syncthreads();
    int excl = s - v + (w > 0 ? wsum[w - 1] : 0);
    if (i < N_NODES) g_rowstart[i] = excl;
    if (tid == 1023) g_part[chunk] = excl + v;
}

// ---------------- scan phase B: tiny serial scan of chunk totals + type offsets ----------------
__global__ void k_scanB() {
    if (threadIdx.x == 0) {
        int acc = 0;
        for (int c = 0; c < NCHUNK; c++) { g_chunkoff[c] = acc; acc += g_part[c]; }
        g_rowstart[N_NODES] = N_EDGES;
        int a2 = 0;
        g_tstart[0] = 0;
        for (int t = 0; t < TN; t++) { a2 += g_ncount[t]; g_tstart[t + 1] = a2; }
        for (int t = 0; t < TN; t++) g_tcur[t] = g_tstart[t];
    }
}

// ---------------- scan phase C: add chunk offsets, init cursors ----------------
__global__ void k_scanC() {
    int i = blockIdx.x * 1024 + threadIdx.x;
    if (i < N_NODES) {
        int r = g_rowstart[i] + g_chunkoff[blockIdx.x];
        g_rowstart[i] = r;
        g_cursor[i] = r;
    }
}

// ---------------- scatter: node order by type, edge metadata into CSR order ----------------
__global__ void k_scatter(const int* __restrict__ ntype, const int* __restrict__ src,
                          const int* __restrict__ dst, const int* __restrict__ etype) {
    int i = blockIdx.x * blockDim.x + threadIdx.x;
    if (i < N_NODES) {
        int t = ntype[i];
        int p = atomicAdd(&g_tcur[t], 1);
        g_node_order[p] = i;
    }
    if (i < N_EDGES) {
        int d = dst[i];
        int p = atomicAdd(&g_cursor[d], 1);
        g_eidx[p] = (etype[i] << 16) | src[i];
    }
}

// ---------------- projection GEMM: k,q,v = x @ W{k,q,v}[t], type-grouped ----------------
__global__ void k_proj(const float* __restrict__ x) {
    int t = blockIdx.y;
    int cnt = g_tstart[t + 1] - g_tstart[t];
    int tile = blockIdx.x * 64;
    if (tile >= cnt) return;

    __shared__ __align__(16) float xs[64][132];
    __shared__ __align__(16) float ws[16][128];
    __shared__ int rows[64];

    int tid = threadIdx.x;
    if (tid < 64) {
        int r = tile + tid;
        rows[tid] = (r < cnt) ? g_node_order[g_tstart[t] + r] : -1;
    }
    __syncthreads();

    for (int i = tid; i < 64 * 32; i += 256) {
        int nr = i >> 5, c4 = i & 31;
        float4 v = make_float4(0.f, 0.f, 0.f, 0.f);
        int g = rows[nr];
        if (g >= 0) v = ((const float4*)x)[g * 32 + c4];
        *((float4*)&xs[nr][c4 * 4]) = v;
    }

    int tc = tid & 31, tr = tid >> 5;
    int h = tc >> 2, j = (tc & 3) * 4;

    for (int mat = 0; mat < 3; mat++) {
        const float* W = g_W + (mat * TN + t) * (DIN * DHID);
        float acc[8][4];
#pragma unroll
        for (int m = 0; m < 8; m++)
#pragma unroll
            for (int c = 0; c < 4; c++) acc[m][c] = 0.f;

        for (int kk = 0; kk < 8; kk++) {
            __syncthreads();
            for (int i = tid; i < 512; i += 256) {
                int r = i >> 5, c4 = i & 31;
                ((float4*)&ws[r][0])[c4] = ((const float4*)(W + (kk * 16 + r) * DHID))[c4];
            }
            __syncthreads();
#pragma unroll
            for (int k2 = 0; k2 < 16; k2++) {
                float4 b = *((const float4*)&ws[k2][tc * 4]);
#pragma unroll
                for (int m = 0; m < 8; m++) {
                    float a = xs[tr * 8 + m][kk * 16 + k2];
                    acc[m][0] += a * b.x; acc[m][1] += a * b.y;
                    acc[m][2] += a * b.z; acc[m][3] += a * b.w;
                }
            }
        }
        float* outb = g_kqv + (mat * NH + h) * (N_NODES * DK);
#pragma unroll
        for (int m = 0; m < 8; m++) {
            int g = rows[tr * 8 + m];
            if (g >= 0) {
                float4 o = make_float4(acc[m][0], acc[m][1], acc[m][2], acc[m][3]);
                *((float4*)&outb[g * DK + j]) = o;
            }
        }
    }
}

// ---------------- relation projection (v only): vt[t,n,h,:] = v[n,h,:] @ msg[t,h] ----------------
__global__ void k_relproj(const float* __restrict__ msg) {
    int lane = threadIdx.x & 31;
    int h = threadIdx.x >> 5;
    int node = blockIdx.x * 32 + lane;
    if (node >= N_NODES) return;

    float vreg[16];
    const float4* vp = (const float4*)(g_kqv + (2 * NH + h) * (N_NODES * DK) + node * DK);
#pragma unroll
    for (int c = 0; c < 4; c++) {
        float4 b = vp[c];
        vreg[c * 4 + 0] = b.x; vreg[c * 4 + 1] = b.y; vreg[c * 4 + 2] = b.z; vreg[c * 4 + 3] = b.w;
    }

    for (int t = 0; t < TE; t++) {
        float vt[16];
#pragma unroll
        for (int z = 0; z < 16; z++) vt[z] = 0.f;
        const float4* M = (const float4*)msg + (t * NH + h) * 64;
#pragma unroll
        for (int i = 0; i < 16; i++) {
            float vi = vreg[i];
#pragma unroll
            for (int jc = 0; jc < 4; jc++) {
                float4 mm = M[i * 4 + jc];
                vt[jc * 4 + 0] += vi * mm.x; vt[jc * 4 + 1] += vi * mm.y;
                vt[jc * 4 + 2] += vi * mm.z; vt[jc * 4 + 3] += vi * mm.w;
            }
        }
        // layout [et][node][h][16]
        float4* VT = (float4*)g_vt + (((size_t)t * N_NODES + node) * NH + h) * 4;
#pragma unroll
        for (int c = 0; c < 4; c++)
            VT[c] = make_float4(vt[c * 4 + 0], vt[c * 4 + 1], vt[c * 4 + 2], vt[c * 4 + 3]);
    }
}

// ---------------- fused attention: qt on-the-fly, logits from L2-resident k, softmax ----------------
// block = dst node, warp = head. Writes exp(e-m) into g_elog and 1/denom into g_dinv.
__global__ void k_att(const float* __restrict__ att, const float* __restrict__ pri) {
    int d = blockIdx.x;
    int tid = threadIdx.x;
    int h = tid >> 5, lane = tid & 31;
    int rs = g_rowstart[d];
    int deg = g_rowstart[d + 1] - rs;
    if (deg == 0) return;

    __shared__ __align__(16) float sqt[NH][TE * DK];   // 4KB

    // q[d] for this head, broadcast to all lanes
    const float* qp = g_kqv + (1 * NH + h) * (N_NODES * DK) + d * DK;
    float4 qf0 = ((const float4*)qp)[0];
    float4 qf1 = ((const float4*)qp)[1];
    float4 qf2 = ((const float4*)qp)[2];
    float4 qf3 = ((const float4*)qp)[3];

    // qt[et][i] = (sum_j A[et,h][i][j] q[j]) * pri[et,h] * scale ; lane = et*4 + ig, i in [ig*4, ig*4+4)
    int et_l = lane >> 2, ig = lane & 3;
    float pv = pri[et_l * NH + h] * 0.25f;
    const float4* Ab = (const float4*)att + (et_l * NH + h) * 64;
#pragma unroll
    for (int ii = 0; ii < 4; ii++) {
        int i = ig * 4 + ii;
        float4 a0 = Ab[i * 4 + 0], a1 = Ab[i * 4 + 1], a2 = Ab[i * 4 + 2], a3 = Ab[i * 4 + 3];
        float acc = a0.x * qf0.x + a0.y * qf0.y + a0.z * qf0.z + a0.w * qf0.w
                  + a1.x * qf1.x + a1.y * qf1.y + a1.z * qf1.z + a1.w * qf1.w
                  + a2.x * qf2.x + a2.y * qf2.y + a2.z * qf2.z + a2.w * qf2.w
                  + a3.x * qf3.x + a3.y * qf3.y + a3.z * qf3.z + a3.w * qf3.w;
        sqt[h][et_l * DK + i] = acc * pv;
    }
    __syncwarp();

    // logits: e_i = k[src_i] . qt[et_i]   (k gather from 25.6MB L2-resident plane set)
    const float* kp = g_kqv + (0 * NH + h) * (N_NODES * DK);
    float* el = g_elog + (size_t)h * N_EDGES + rs;
    float m = -1e30f;
    for (int i = lane; i < deg; i += 32) {
        int e = g_eidx[rs + i];
        int et = e >> 16, s = e & 0xFFFF;
        const float4* kv = (const float4*)(kp + s * DK);
        const float4* qt = (const float4*)&sqt[h][et * DK];
        float4 k0 = kv[0], k1 = kv[1], k2 = kv[2], k3 = kv[3];
        float4 t0 = qt[0], t1 = qt[1], t2 = qt[2], t3 = qt[3];
        float acc = k0.x * t0.x + k0.y * t0.y + k0.z * t0.z + k0.w * t0.w
                  + k1.x * t1.x + k1.y * t1.y + k1.z * t1.z + k1.w * t1.w
                  + k2.x * t2.x + k2.y * t2.y + k2.z * t2.z + k2.w * t2.w
                  + k3.x * t3.x + k3.y * t3.y + k3.z * t3.z + k3.w * t3.w;
        el[i] = acc;
        m = fmaxf(m, acc);
    }
#pragma unroll
    for (int o = 16; o > 0; o >>= 1) m = fmaxf(m, __shfl_xor_sync(0xffffffffu, m, o));
    float ssum = 0.f;
    for (int i = lane; i < deg; i += 32) {
        float v = expf(el[i] - m);
        el[i] = v;
        ssum += v;
    }
#pragma unroll
    for (int o = 16; o > 0; o >>= 1) ssum += __shfl_xor_sync(0xffffffffu, ssum, o);
    if (lane == 0) g_dinv[d * NH + h] = 1.f / ssum;
}

// ---------------- aggregation: single weighted-sum pass over CSR rows ----------------
__global__ void k_agg() {
    int d = blockIdx.x;
    int tid = threadIdx.x;
    int h = tid >> 5, lane = tid & 31;
    int rs = g_rowstart[d];
    int deg = g_rowstart[d + 1] - rs;
    int j = lane & 15, half = lane >> 4;
    if (deg == 0) {
        if (lane < 16) g_agg[d * DHID + h * DK + j] = 0.f;
        return;
    }
    float inv = g_dinv[d * NH + h];
    const float* el = g_elog + (size_t)h * N_EDGES + rs;
    float acc = 0.f;
    for (int i = half; i < deg; i += 2) {
        float a = el[i];
        int e = g_eidx[rs + i];
        int et = e >> 16, s = e & 0xFFFF;
        acc += a * g_vt[(((size_t)et * N_NODES + s) * NH + h) * DK + j];
    }
    acc += __shfl_xor_sync(0xffffffffu, acc, 16);
    if (lane < 16) g_agg[d * DHID + h * DK + j] = acc * inv;
}

// ---------------- output: relu(agg @ Wa[t] + x @ loop + bias) ----------------
__global__ void k_out(const float* __restrict__ x, const float* __restrict__ loopw,
                      const float* __restrict__ bias, float* __restrict__ out) {
    int t = blockIdx.y;
    int cnt = g_tstart[t + 1] - g_tstart[t];
    int tile = blockIdx.x * 64;
    if (tile >= cnt) return;

    __shared__ __align__(16) float xs[64][132];
    __shared__ __align__(16) float ws[16][128];
    __shared__ int rows[64];

    int tid = threadIdx.x;
    if (tid < 64) {
        int r = tile + tid;
        rows[tid] = (r < cnt) ? g_node_order[g_tstart[t] + r] : -1;
    }
    __syncthreads();

    int tc = tid & 31, tr = tid >> 5;
    float acc[8][4];
#pragma unroll
    for (int m = 0; m < 8; m++)
#pragma unroll
        for (int c = 0; c < 4; c++) acc[m][c] = 0.f;

    for (int ph = 0; ph < 2; ph++) {
        const float* A = (ph == 0) ? g_agg : x;
        const float* W = (ph == 0) ? (g_W + (3 * TN + t) * (DIN * DHID)) : loopw;
        __syncthreads();
        for (int i = tid; i < 64 * 32; i += 256) {
            int nr = i >> 5, c4 = i & 31;
            float4 v = make_float4(0.f, 0.f, 0.f, 0.f);
            int g = rows[nr];
            if (g >= 0) v = ((const float4*)A)[g * 32 + c4];
            *((float4*)&xs[nr][c4 * 4]) = v;
        }
        for (int kk = 0; kk < 8; kk++) {
            __syncthreads();
            for (int i = tid; i < 512; i += 256) {
                int r = i >> 5, c4 = i & 31;
                ((float4*)&ws[r][0])[c4] = ((const float4*)(W + (kk * 16 + r) * DHID))[c4];
            }
            __syncthreads();
#pragma unroll
            for (int k2 = 0; k2 < 16; k2++) {
                float4 b = *((const float4*)&ws[k2][tc * 4]);
#pragma unroll
                for (int m = 0; m < 8; m++) {
                    float a = xs[tr * 8 + m][kk * 16 + k2];
                    acc[m][0] += a * b.x; acc[m][1] += a * b.y;
                    acc[m][2] += a * b.z; acc[m][3] += a * b.w;
                }
            }
        }
    }

    float4 bv = *((const float4*)&bias[tc * 4]);
#pragma unroll
    for (int m = 0; m < 8; m++) {
        int g = rows[tr * 8 + m];
        if (g >= 0) {
            float4 o;
            o.x = fmaxf(acc[m][0] + bv.x, 0.f);
            o.y = fmaxf(acc[m][1] + bv.y, 0.f);
            o.z = fmaxf(acc[m][2] + bv.z, 0.f);
            o.w = fmaxf(acc[m][3] + bv.w, 0.f);
            *((float4*)&out[g * DHID + tc * 4]) = o;
        }
    }
}

// ---------------- launch ----------------
extern "C" void kernel_launch(void* const* d_in, const int* in_sizes, int n_in,
                              void* d_out, int out_size) {
    const float* x     = (const float*)d_in[0];
    const int*   ntype = (const int*)d_in[1];
    const int*   src   = (const int*)d_in[2];
    const int*   dst   = (const int*)d_in[3];
    const int*   etype = (const int*)d_in[4];
    const float* wck   = (const float*)d_in[5];
    const float* wbk   = (const float*)d_in[6];
    const float* wcq   = (const float*)d_in[7];
    const float* wbq   = (const float*)d_in[8];
    const float* wcv   = (const float*)d_in[9];
    const float* wbv   = (const float*)d_in[10];
    const float* wca   = (const float*)d_in[11];
    const float* wba   = (const float*)d_in[12];
    const float* pri   = (const float*)d_in[13];
    const float* att   = (const float*)d_in[14];
    const float* msg   = (const float*)d_in[15];
    const float* loopw = (const float*)d_in[16];
    const float* bias  = (const float*)d_in[17];
    float* out = (float*)d_out;

    k_init<<<(N_NODES + 255) / 256, 256>>>();
    k_prepW<<<(4 * TN * DIN * DHID + 255) / 256, 256>>>(wck, wbk, wcq, wbq, wcv, wbv, wca, wba);
    k_count<<<(N_EDGES + 255) / 256, 256>>>(ntype, dst);
    k_scanA<<<NCHUNK, 1024>>>();
    k_scanB<<<1, 32>>>();
    k_scanC<<<NCHUNK, 1024>>>();
    k_scatter<<<(N_EDGES + 255) / 256, 256>>>(ntype, src, dst, etype);
    k_proj<<<dim3((N_NODES + 63) / 64, TN), 256>>>(x);
    k_relproj<<<(N_NODES + 31) / 32, 256>>>(msg);
    k_att<<<N_NODES, 256>>>(att, pri);
    k_agg<<<N_NODES, 256>>>();
    k_out<<<dim3((N_NODES + 63) / 64, TN), 256>>>(x, loopw, bias, out);
}

// round 4
// speedup vs baseline: 1.6264x; 1.6264x over previous
#include <cuda_runtime.h>

#define N_NODES 50000
#define N_EDGES 800000
#define DIN 128
#define DHID 128
#define NH 8
#define DK 16
#define TN 8
#define TE 8
#define NB 4
#define NCHUNK ((N_NODES + 1023) / 1024)

// ---------------- scratch (static device memory; no allocations) ----------------
__device__ float g_W[4 * TN * DIN * DHID];            // Wk,Wq,Wv,Wa  [4][8][128*128]
__device__ float g_kqv[3 * NH * N_NODES * DK];        // k,q,v in [mat][h][n][16] layout
__device__ float g_kt[TE * NH * N_NODES * DK];        // k@att, [et][h][n][16]  204.8 MB
__device__ float g_vt[TE * NH * N_NODES * DK];        // v@msg, [et][h][n][16]  204.8 MB
__device__ float g_elog[(size_t)NH * N_EDGES];        // logits -> exp values [h][p]
__device__ int   g_mkey[N_NODES * NH];                // max logit per (dst,h), monotone int key
__device__ float g_agg[N_NODES * DHID];               // aggregated messages [n][128]
__device__ int   g_deg[N_NODES];
__device__ int   g_rowstart[N_NODES + 1];
__device__ int   g_cursor[N_NODES];
__device__ int   g_eidx[N_EDGES];                     // et*(NH*N) + src, sorted by dst
__device__ int   g_dst_s[N_EDGES];                    // dst, sorted (CSR order)
__device__ int   g_node_order[N_NODES];
__device__ int   g_ncount[TN];
__device__ int   g_tstart[TN + 1];
__device__ int   g_tcur[TN];
__device__ int   g_part[NCHUNK];
__device__ int   g_chunkoff[NCHUNK];

// monotone float<->int key (order-preserving, so atomicMax is deterministic)
__device__ __forceinline__ int   fkey(float f) { int b = __float_as_int(f); return b >= 0 ? b : (b ^ 0x7FFFFFFF); }
__device__ __forceinline__ float fdec(int k)   { return __int_as_float(k >= 0 ? k : (k ^ 0x7FFFFFFF)); }

// ---------------- init: zero counters, -inf max keys ----------------
__global__ void k_init() {
    int i = blockIdx.x * blockDim.x + threadIdx.x;
    if (i < N_NODES) g_deg[i] = 0;
    if (i < TN) g_ncount[i] = 0;
    if (i < N_NODES * NH) g_mkey[i] = 0x80000000;   // INT_MIN <= every key
}

// ---------------- build per-type weight matrices W[t] = comp[t] @ basis ----------------
__global__ void k_prepW(const float* __restrict__ ck, const float* __restrict__ bk,
                        const float* __restrict__ cq, const float* __restrict__ bq,
                        const float* __restrict__ cv, const float* __restrict__ bv,
                        const float* __restrict__ ca, const float* __restrict__ ba) {
    int idx = blockIdx.x * blockDim.x + threadIdx.x;           // 4 * 8 * 16384
    if (idx >= 4 * TN * DIN * DHID) return;
    int m  = idx >> 17;           // matrix id
    int r  = idx & 131071;
    int t  = r >> 14;             // type
    int io = r & 16383;
    const float* comp;
    const float* basis;
    if (m == 0)      { comp = ck; basis = bk; }
    else if (m == 1) { comp = cq; basis = bq; }
    else if (m == 2) { comp = cv; basis = bv; }
    else             { comp = ca; basis = ba; }
    float acc = 0.f;
#pragma unroll
    for (int b = 0; b < NB; b++)
        acc += comp[t * NB + b] * basis[b * (DIN * DHID) + io];
    g_W[idx] = acc;
}

// ---------------- counts: node types + in-degrees ----------------
__global__ void k_count(const int* __restrict__ ntype, const int* __restrict__ dst) {
    int i = blockIdx.x * blockDim.x + threadIdx.x;
    if (i < N_NODES) atomicAdd(&g_ncount[ntype[i]], 1);
    if (i < N_EDGES) atomicAdd(&g_deg[dst[i]], 1);
}

// ---------------- parallel scan phase A: per-chunk exclusive scan + chunk totals ----------------
__global__ void k_scanA() {
    __shared__ int wsum[32];
    int tid = threadIdx.x;
    int chunk = blockIdx.x;
    int i = chunk * 1024 + tid;
    int v = (i < N_NODES) ? g_deg[i] : 0;
    int lane = tid & 31, w = tid >> 5;
    int s = v;
#pragma unroll
    for (int o = 1; o < 32; o <<= 1) {
        int t = __shfl_up_sync(0xffffffffu, s, o);
        if (lane >= o) s += t;
    }
    if (lane == 31) wsum[w] = s;
    __syncthreads();
    if (w == 0) {
        int x = wsum[lane];
#pragma unroll
        for (int o = 1; o < 32; o <<= 1) {
            int t = __shfl_up_sync(0xffffffffu, x, o);
            if (lane >= o) x += t;
        }
        wsum[lane] = x;
    }
    __syncthreads();
    int excl = s - v + (w > 0 ? wsum[w - 1] : 0);
    if (i < N_NODES) g_rowstart[i] = excl;
    if (tid == 1023) g_part[chunk] = excl + v;
}

// ---------------- scan phase B: tiny serial scan of chunk totals + type offsets ----------------
__global__ void k_scanB() {
    if (threadIdx.x == 0) {
        int acc = 0;
        for (int c = 0; c < NCHUNK; c++) { g_chunkoff[c] = acc; acc += g_part[c]; }
        g_rowstart[N_NODES] = N_EDGES;
        int a2 = 0;
        g_tstart[0] = 0;
        for (int t = 0; t < TN; t++) { a2 += g_ncount[t]; g_tstart[t + 1] = a2; }
        for (int t = 0; t < TN; t++) g_tcur[t] = g_tstart[t];
    }
}

// ---------------- scan phase C: add chunk offsets, init cursors ----------------
__global__ void k_scanC() {
    int i = blockIdx.x * 1024 + threadIdx.x;
    if (i < N_NODES) {
        int r = g_rowstart[i] + g_chunkoff[blockIdx.x];
        g_rowstart[i] = r;
        g_cursor[i] = r;
    }
}

// ---------------- scatter: node order by type, edge metadata into CSR order ----------------
__global__ void k_scatter(const int* __restrict__ ntype, const int* __restrict__ src,
                          const int* __restrict__ dst, const int* __restrict__ etype) {
    int i = blockIdx.x * blockDim.x + threadIdx.x;
    if (i < N_NODES) {
        int t = ntype[i];
        int p = atomicAdd(&g_tcur[t], 1);
        g_node_order[p] = i;
    }
    if (i < N_EDGES) {
        int d = dst[i];
        int p = atomicAdd(&g_cursor[d], 1);
        g_eidx[p] = etype[i] * (NH * N_NODES) + src[i];
        g_dst_s[p] = d;
    }
}

// ---------------- projection GEMM: k,q,v = x @ W{k,q,v}[t], type-grouped ----------------
__global__ void k_proj(const float* __restrict__ x) {
    int t = blockIdx.y;
    int cnt = g_tstart[t + 1] - g_tstart[t];
    int tile = blockIdx.x * 64;
    if (tile >= cnt) return;

    __shared__ __align__(16) float xs[64][132];
    __shared__ __align__(16) float ws[16][128];
    __shared__ int rows[64];

    int tid = threadIdx.x;
    if (tid < 64) {
        int r = tile + tid;
        rows[tid] = (r < cnt) ? g_node_order[g_tstart[t] + r] : -1;
    }
    __syncthreads();

    for (int i = tid; i < 64 * 32; i += 256) {
        int nr = i >> 5, c4 = i & 31;
        float4 v = make_float4(0.f, 0.f, 0.f, 0.f);
        int g = rows[nr];
        if (g >= 0) v = ((const float4*)x)[g * 32 + c4];
        *((float4*)&xs[nr][c4 * 4]) = v;
    }

    int tc = tid & 31, tr = tid >> 5;
    int h = tc >> 2, j = (tc & 3) * 4;

    for (int mat = 0; mat < 3; mat++) {
        const float* W = g_W + (mat * TN + t) * (DIN * DHID);
        float acc[8][4];
#pragma unroll
        for (int m = 0; m < 8; m++)
#pragma unroll
            for (int c = 0; c < 4; c++) acc[m][c] = 0.f;

        for (int kk = 0; kk < 8; kk++) {
            __syncthreads();
            for (int i = tid; i < 512; i += 256) {
                int r = i >> 5, c4 = i & 31;
                ((float4*)&ws[r][0])[c4] = ((const float4*)(W + (kk * 16 + r) * DHID))[c4];
            }
            __syncthreads();
#pragma unroll
            for (int k2 = 0; k2 < 16; k2++) {
                float4 b = *((const float4*)&ws[k2][tc * 4]);
#pragma unroll
                for (int m = 0; m < 8; m++) {
                    float a = xs[tr * 8 + m][kk * 16 + k2];
                    acc[m][0] += a * b.x; acc[m][1] += a * b.y;
                    acc[m][2] += a * b.z; acc[m][3] += a * b.w;
                }
            }
        }
        float* outb = g_kqv + (mat * NH + h) * (N_NODES * DK);
#pragma unroll
        for (int m = 0; m < 8; m++) {
            int g = rows[tr * 8 + m];
            if (g >= 0) {
                float4 o = make_float4(acc[m][0], acc[m][1], acc[m][2], acc[m][3]);
                *((float4*)&outb[g * DK + j]) = o;
            }
        }
    }
}

// ---------------- relation projections: kt[t,h,n]=k@att[t,h], vt[t,h,n]=v@msg[t,h] ----------------
__global__ void k_relproj(const float* __restrict__ att, const float* __restrict__ msg) {
    int lane = threadIdx.x & 31;
    int h = threadIdx.x >> 5;
    int node = blockIdx.x * 32 + lane;
    if (node >= N_NODES) return;

    float kreg[16], vreg[16];
    const float4* kp = (const float4*)(g_kqv + (0 * NH + h) * (N_NODES * DK) + node * DK);
    const float4* vp = (const float4*)(g_kqv + (2 * NH + h) * (N_NODES * DK) + node * DK);
#pragma unroll
    for (int c = 0; c < 4; c++) {
        float4 a = kp[c];
        kreg[c * 4 + 0] = a.x; kreg[c * 4 + 1] = a.y; kreg[c * 4 + 2] = a.z; kreg[c * 4 + 3] = a.w;
        float4 b = vp[c];
        vreg[c * 4 + 0] = b.x; vreg[c * 4 + 1] = b.y; vreg[c * 4 + 2] = b.z; vreg[c * 4 + 3] = b.w;
    }

    for (int t = 0; t < TE; t++) {
        float kt[16], vt[16];
#pragma unroll
        for (int z = 0; z < 16; z++) { kt[z] = 0.f; vt[z] = 0.f; }
        const float4* A = (const float4*)att + (t * NH + h) * 64;
        const float4* M = (const float4*)msg + (t * NH + h) * 64;
#pragma unroll
        for (int i = 0; i < 16; i++) {
            float ki = kreg[i], vi = vreg[i];
#pragma unroll
            for (int jc = 0; jc < 4; jc++) {
                float4 a = A[i * 4 + jc];
                kt[jc * 4 + 0] += ki * a.x; kt[jc * 4 + 1] += ki * a.y;
                kt[jc * 4 + 2] += ki * a.z; kt[jc * 4 + 3] += ki * a.w;
                float4 mm = M[i * 4 + jc];
                vt[jc * 4 + 0] += vi * mm.x; vt[jc * 4 + 1] += vi * mm.y;
                vt[jc * 4 + 2] += vi * mm.z; vt[jc * 4 + 3] += vi * mm.w;
            }
        }
        float4* KT = (float4*)g_kt + ((size_t)(t * NH + h) * N_NODES + node) * 4;
        float4* VT = (float4*)g_vt + ((size_t)(t * NH + h) * N_NODES + node) * 4;
#pragma unroll
        for (int c = 0; c < 4; c++) {
            KT[c] = make_float4(kt[c * 4 + 0], kt[c * 4 + 1], kt[c * 4 + 2], kt[c * 4 + 3]);
            VT[c] = make_float4(vt[c * 4 + 0], vt[c * 4 + 1], vt[c * 4 + 2], vt[c * 4 + 3]);
        }
    }
}

// ---------------- edge attention logits + deterministic running max ----------------
__global__ void k_logits(const float* __restrict__ pri) {
    int p = blockIdx.x * blockDim.x + threadIdx.x;
    int h = blockIdx.y;
    if (p >= N_EDGES) return;
    int eidx = g_eidx[p];                 // et*(NH*N) + src
    int d = g_dst_s[p];
    int et = eidx / (NH * N_NODES);
    const float4* kt = (const float4*)g_kt + ((size_t)eidx + (size_t)h * N_NODES) * 4;
    const float4* qq = (const float4*)(g_kqv + (1 * NH + h) * (N_NODES * DK) + d * DK);
    float acc = 0.f;
#pragma unroll
    for (int c = 0; c < 4; c++) {
        float4 a = kt[c];
        float4 b = qq[c];
        acc += a.x * b.x + a.y * b.y + a.z * b.z + a.w * b.w;
    }
    float e = acc * pri[et * NH + h] * 0.25f;
    g_elog[(size_t)h * N_EDGES + p] = e;
    atomicMax(&g_mkey[d * NH + h], fkey(e));   // order-independent -> deterministic
}

// ---------------- edge softmax + aggregation (2 passes; exp computed once) ----------------
__global__ void k_agg() {
    int d = blockIdx.x;
    int h = threadIdx.x >> 5;
    int lane = threadIdx.x & 31;
    int rs = g_rowstart[d];
    int deg = g_rowstart[d + 1] - rs;
    int j = lane & 15, half = lane >> 4;
    float* el = g_elog + (size_t)h * N_EDGES + rs;

    if (deg == 0) {
        if (lane < 16) g_agg[d * DHID + h * DK + j] = 0.f;
        return;
    }
    float m = fdec(g_mkey[d * NH + h]);
    // pass 1: exp once (cache into elog) + denom
    float s = 0.f;
    for (int i = lane; i < deg; i += 32) {
        float v = __expf(el[i] - m);
        el[i] = v;
        s += v;
    }
#pragma unroll
    for (int o = 16; o > 0; o >>= 1) s += __shfl_xor_sync(0xffffffffu, s, o);
    float inv = 1.f / s;
    // pass 2: weighted sum of vt (two edges in flight: lanes 0-15 / 16-31)
    float acc = 0.f;
    for (int i = half; i < deg; i += 2) {
        float a = el[i];
        int eidx = g_eidx[rs + i];
        acc += a * g_vt[((size_t)eidx + (size_t)h * N_NODES) * DK + j];
    }
    acc += __shfl_xor_sync(0xffffffffu, acc, 16);
    if (lane < 16) g_agg[d * DHID + h * DK + j] = acc * inv;
}

// ---------------- output: relu(agg @ Wa[t] + x @ loop + bias) ----------------
__global__ void k_out(const float* __restrict__ x, const float* __restrict__ loopw,
                      const float* __restrict__ bias, float* __restrict__ out) {
    int t = blockIdx.y;
    int cnt = g_tstart[t + 1] - g_tstart[t];
    int tile = blockIdx.x * 64;
    if (tile >= cnt) return;

    __shared__ __align__(16) float xs[64][132];
    __shared__ __align__(16) float ws[16][128];
    __shared__ int rows[64];

    int tid = threadIdx.x;
    if (tid < 64) {
        int r = tile + tid;
        rows[tid] = (r < cnt) ? g_node_order[g_tstart[t] + r] : -1;
    }
    __syncthreads();

    int tc = tid & 31, tr = tid >> 5;
    float acc[8][4];
#pragma unroll
    for (int m = 0; m < 8; m++)
#pragma unroll
        for (int c = 0; c < 4; c++) acc[m][c] = 0.f;

    for (int ph = 0; ph < 2; ph++) {
        const float* A = (ph == 0) ? g_agg : x;
        const float* W = (ph == 0) ? (g_W + (3 * TN + t) * (DIN * DHID)) : loopw;
        __syncthreads();
        for (int i = tid; i < 64 * 32; i += 256) {
            int nr = i >> 5, c4 = i & 31;
            float4 v = make_float4(0.f, 0.f, 0.f, 0.f);
            int g = rows[nr];
            if (g >= 0) v = ((const float4*)A)[g * 32 + c4];
            *((float4*)&xs[nr][c4 * 4]) = v;
        }
        for (int kk = 0; kk < 8; kk++) {
            __syncthreads();
            for (int i = tid; i < 512; i += 256) {
                int r = i >> 5, c4 = i & 31;
                ((float4*)&ws[r][0])[c4] = ((const float4*)(W + (kk * 16 + r) * DHID))[c4];
            }
            __syncthreads();
#pragma unroll
            for (int k2 = 0; k2 < 16; k2++) {
                float4 b = *((const float4*)&ws[k2][tc * 4]);
#pragma unroll
                for (int m = 0; m < 8; m++) {
                    float a = xs[tr * 8 + m][kk * 16 + k2];
                    acc[m][0] += a * b.x; acc[m][1] += a * b.y;
                    acc[m][2] += a * b.z; acc[m][3] += a * b.w;
                }
            }
        }
    }

    float4 bv = *((const float4*)&bias[tc * 4]);
#pragma unroll
    for (int m = 0; m < 8; m++) {
        int g = rows[tr * 8 + m];
        if (g >= 0) {
            float4 o;
            o.x = fmaxf(acc[m][0] + bv.x, 0.f);
            o.y = fmaxf(acc[m][1] + bv.y, 0.f);
            o.z = fmaxf(acc[m][2] + bv.z, 0.f);
            o.w = fmaxf(acc[m][3] + bv.w, 0.f);
            *((float4*)&out[g * DHID + tc * 4]) = o;
        }
    }
}

// ---------------- launch ----------------
extern "C" void kernel_launch(void* const* d_in, const int* in_sizes, int n_in,
                              void* d_out, int out_size) {
    const float* x     = (const float*)d_in[0];
    const int*   ntype = (const int*)d_in[1];
    const int*   src   = (const int*)d_in[2];
    const int*   dst   = (const int*)d_in[3];
    const int*   etype = (const int*)d_in[4];
    const float* wck   = (const float*)d_in[5];
    const float* wbk   = (const float*)d_in[6];
    const float* wcq   = (const float*)d_in[7];
    const float* wbq   = (const float*)d_in[8];
    const float* wcv   = (const float*)d_in[9];
    const float* wbv   = (const float*)d_in[10];
    const float* wca   = (const float*)d_in[11];
    const float* wba   = (const float*)d_in[12];
    const float* pri   = (const float*)d_in[13];
    const float* att   = (const float*)d_in[14];
    const float* msg   = (const float*)d_in[15];
    const float* loopw = (const float*)d_in[16];
    const float* bias  = (const float*)d_in[17];
    float* out = (float*)d_out;

    k_init<<<(N_NODES * NH + 255) / 256, 256>>>();
    k_prepW<<<(4 * TN * DIN * DHID + 255) / 256, 256>>>(wck, wbk, wcq, wbq, wcv, wbv, wca, wba);
    k_count<<<(N_EDGES + 255) / 256, 256>>>(ntype, dst);
    k_scanA<<<NCHUNK, 1024>>>();
    k_scanB<<<1, 32>>>();
    k_scanC<<<NCHUNK, 1024>>>();
    k_scatter<<<(N_EDGES + 255) / 256, 256>>>(ntype, src, dst, etype);
    k_proj<<<dim3((N_NODES + 63) / 64, TN), 256>>>(x);
    k_relproj<<<(N_NODES + 31) / 32, 256>>>(att, msg);
    k_logits<<<dim3((N_EDGES + 255) / 256, NH), 256>>>(pri);
    k_agg<<<N_NODES, 256>>>();
    k_out<<<dim3((N_NODES + 63) / 64, TN), 256>>>(x, loopw, bias, out);
}

// round 5
// speedup vs baseline: 1.7064x; 1.0492x over previous
#include <cuda_runtime.h>
#include <cuda_fp16.h>

#define N_NODES 50000
#define N_EDGES 800000
#define DIN 128
#define DHID 128
#define NH 8
#define DK 16
#define TN 8
#define TE 8
#define NB 4
#define NCHUNK ((N_NODES + 1023) / 1024)

// ---------------- scratch (static device memory; no allocations) ----------------
__device__ float  g_W[4 * TN * DIN * DHID];            // Wk,Wq,Wv,Wa  [4][8][128*128]
__device__ float  g_kqv[3 * NH * N_NODES * DK];        // k,q,v in [mat][h][n][16] layout
__device__ __half g_kt_h[(size_t)TE * NH * N_NODES * DK]; // (k@att)*pri*scale, fp16, 102.4 MB
__device__ __half g_vt_h[(size_t)TE * NH * N_NODES * DK]; // v@msg, fp16, 102.4 MB
__device__ float  g_elog[(size_t)NH * N_EDGES];        // logits -> exp values [h][p]
__device__ int    g_mkey[N_NODES * NH];                // max logit per (dst,h), monotone int key
__device__ float  g_agg[N_NODES * DHID];               // aggregated messages [n][128]
__device__ int    g_deg[N_NODES];
__device__ int    g_rowstart[N_NODES + 1];
__device__ int    g_cursor[N_NODES];
__device__ int    g_eidx[N_EDGES];                     // et*(NH*N) + src, sorted by dst
__device__ int    g_dst_s[N_EDGES];                    // dst, sorted (CSR order)
__device__ int    g_node_order[N_NODES];
__device__ int    g_ncount[TN];
__device__ int    g_tstart[TN + 1];
__device__ int    g_tcur[TN];
__device__ int    g_part[NCHUNK];
__device__ int    g_chunkoff[NCHUNK];

// monotone float<->int key (order-preserving, so atomicMax is deterministic)
__device__ __forceinline__ int   fkey(float f) { int b = __float_as_int(f); return b >= 0 ? b : (b ^ 0x7FFFFFFF); }
__device__ __forceinline__ float fdec(int k)   { return __int_as_float(k >= 0 ? k : (k ^ 0x7FFFFFFF)); }

// ---------------- init: zero counters, -inf max keys ----------------
__global__ void k_init() {
    int i = blockIdx.x * blockDim.x + threadIdx.x;
    if (i < N_NODES) g_deg[i] = 0;
    if (i < TN) g_ncount[i] = 0;
    if (i < N_NODES * NH) g_mkey[i] = 0x80000000;   // INT_MIN <= every key
}

// ---------------- build per-type weight matrices W[t] = comp[t] @ basis ----------------
__global__ void k_prepW(const float* __restrict__ ck, const float* __restrict__ bk,
                        const float* __restrict__ cq, const float* __restrict__ bq,
                        const float* __restrict__ cv, const float* __restrict__ bv,
                        const float* __restrict__ ca, const float* __restrict__ ba) {
    int idx = blockIdx.x * blockDim.x + threadIdx.x;           // 4 * 8 * 16384
    if (idx >= 4 * TN * DIN * DHID) return;
    int m  = idx >> 17;           // matrix id
    int r  = idx & 131071;
    int t  = r >> 14;             // type
    int io = r & 16383;
    const float* comp;
    const float* basis;
    if (m == 0)      { comp = ck; basis = bk; }
    else if (m == 1) { comp = cq; basis = bq; }
    else if (m == 2) { comp = cv; basis = bv; }
    else             { comp = ca; basis = ba; }
    float acc = 0.f;
#pragma unroll
    for (int b = 0; b < NB; b++)
        acc += comp[t * NB + b] * basis[b * (DIN * DHID) + io];
    g_W[idx] = acc;
}

// ---------------- counts: node types + in-degrees ----------------
__global__ void k_count(const int* __restrict__ ntype, const int* __restrict__ dst) {
    int i = blockIdx.x * blockDim.x + threadIdx.x;
    if (i < N_NODES) atomicAdd(&g_ncount[ntype[i]], 1);
    if (i < N_EDGES) atomicAdd(&g_deg[dst[i]], 1);
}

// ---------------- parallel scan phase A: per-chunk exclusive scan + chunk totals ----------------
__global__ void k_scanA() {
    __shared__ int wsum[32];
    int tid = threadIdx.x;
    int chunk = blockIdx.x;
    int i = chunk * 1024 + tid;
    int v = (i < N_NODES) ? g_deg[i] : 0;
    int lane = tid & 31, w = tid >> 5;
    int s = v;
#pragma unroll
    for (int o = 1; o < 32; o <<= 1) {
        int t = __shfl_up_sync(0xffffffffu, s, o);
        if (lane >= o) s += t;
    }
    if (lane == 31) wsum[w] = s;
    __syncthreads();
    if (w == 0) {
        int x = wsum[lane];
#pragma unroll
        for (int o = 1; o < 32; o <<= 1) {
            int t = __shfl_up_sync(0xffffffffu, x, o);
            if (lane >= o) x += t;
        }
        wsum[lane] = x;
    }
    __syncthreads();
    int excl = s - v + (w > 0 ? wsum[w - 1] : 0);
    if (i < N_NODES) g_rowstart[i] = excl;
    if (tid == 1023) g_part[chunk] = excl + v;
}

// ---------------- scan phase B: tiny serial scan of chunk totals + type offsets ----------------
__global__ void k_scanB() {
    if (threadIdx.x == 0) {
        int acc = 0;
        for (int c = 0; c < NCHUNK; c++) { g_chunkoff[c] = acc; acc += g_part[c]; }
        g_rowstart[N_NODES] = N_EDGES;
        int a2 = 0;
        g_tstart[0] = 0;
        for (int t = 0; t < TN; t++) { a2 += g_ncount[t]; g_tstart[t + 1] = a2; }
        for (int t = 0; t < TN; t++) g_tcur[t] = g_tstart[t];
    }
}

// ---------------- scan phase C: add chunk offsets, init cursors ----------------
__global__ void k_scanC() {
    int i = blockIdx.x * 1024 + threadIdx.x;
    if (i < N_NODES) {
        int r = g_rowstart[i] + g_chunkoff[blockIdx.x];
        g_rowstart[i] = r;
        g_cursor[i] = r;
    }
}

// ---------------- scatter: node order by type, edge metadata into CSR order ----------------
__global__ void k_scatter(const int* __restrict__ ntype, const int* __restrict__ src,
                          const int* __restrict__ dst, const int* __restrict__ etype) {
    int i = blockIdx.x * blockDim.x + threadIdx.x;
    if (i < N_NODES) {
        int t = ntype[i];
        int p = atomicAdd(&g_tcur[t], 1);
        g_node_order[p] = i;
    }
    if (i < N_EDGES) {
        int d = dst[i];
        int p = atomicAdd(&g_cursor[d], 1);
        g_eidx[p] = etype[i] * (NH * N_NODES) + src[i];
        g_dst_s[p] = d;
    }
}

// ---------------- projection GEMM: k,q,v = x @ W{k,q,v}[t], type-grouped ----------------
__global__ void k_proj(const float* __restrict__ x) {
    int t = blockIdx.y;
    int cnt = g_tstart[t + 1] - g_tstart[t];
    int tile = blockIdx.x * 64;
    if (tile >= cnt) return;

    __shared__ __align__(16) float xs[64][132];
    __shared__ __align__(16) float ws[16][128];
    __shared__ int rows[64];

    int tid = threadIdx.x;
    if (tid < 64) {
        int r = tile + tid;
        rows[tid] = (r < cnt) ? g_node_order[g_tstart[t] + r] : -1;
    }
    __syncthreads();

    for (int i = tid; i < 64 * 32; i += 256) {
        int nr = i >> 5, c4 = i & 31;
        float4 v = make_float4(0.f, 0.f, 0.f, 0.f);
        int g = rows[nr];
        if (g >= 0) v = ((const float4*)x)[g * 32 + c4];
        *((float4*)&xs[nr][c4 * 4]) = v;
    }

    int tc = tid & 31, tr = tid >> 5;
    int h = tc >> 2, j = (tc & 3) * 4;

    for (int mat = 0; mat < 3; mat++) {
        const float* W = g_W + (mat * TN + t) * (DIN * DHID);
        float acc[8][4];
#pragma unroll
        for (int m = 0; m < 8; m++)
#pragma unroll
            for (int c = 0; c < 4; c++) acc[m][c] = 0.f;

        for (int kk = 0; kk < 8; kk++) {
            __syncthreads();
            for (int i = tid; i < 512; i += 256) {
                int r = i >> 5, c4 = i & 31;
                ((float4*)&ws[r][0])[c4] = ((const float4*)(W + (kk * 16 + r) * DHID))[c4];
            }
            __syncthreads();
#pragma unroll
            for (int k2 = 0; k2 < 16; k2++) {
                float4 b = *((const float4*)&ws[k2][tc * 4]);
#pragma unroll
                for (int m = 0; m < 8; m++) {
                    float a = xs[tr * 8 + m][kk * 16 + k2];
                    acc[m][0] += a * b.x; acc[m][1] += a * b.y;
                    acc[m][2] += a * b.z; acc[m][3] += a * b.w;
                }
            }
        }
        float* outb = g_kqv + (mat * NH + h) * (N_NODES * DK);
#pragma unroll
        for (int m = 0; m < 8; m++) {
            int g = rows[tr * 8 + m];
            if (g >= 0) {
                float4 o = make_float4(acc[m][0], acc[m][1], acc[m][2], acc[m][3]);
                *((float4*)&outb[g * DK + j]) = o;
            }
        }
    }
}

// ---------------- relation projections -> fp16: kt=(k@att)*pri*scale, vt=v@msg ----------------
__global__ void k_relproj(const float* __restrict__ att, const float* __restrict__ msg,
                          const float* __restrict__ pri) {
    int lane = threadIdx.x & 31;
    int h = threadIdx.x >> 5;
    int node = blockIdx.x * 32 + lane;
    if (node >= N_NODES) return;

    float kreg[16], vreg[16];
    const float4* kp = (const float4*)(g_kqv + (0 * NH + h) * (N_NODES * DK) + node * DK);
    const float4* vp = (const float4*)(g_kqv + (2 * NH + h) * (N_NODES * DK) + node * DK);
#pragma unroll
    for (int c = 0; c < 4; c++) {
        float4 a = kp[c];
        kreg[c * 4 + 0] = a.x; kreg[c * 4 + 1] = a.y; kreg[c * 4 + 2] = a.z; kreg[c * 4 + 3] = a.w;
        float4 b = vp[c];
        vreg[c * 4 + 0] = b.x; vreg[c * 4 + 1] = b.y; vreg[c * 4 + 2] = b.z; vreg[c * 4 + 3] = b.w;
    }

    for (int t = 0; t < TE; t++) {
        float kt[16], vt[16];
#pragma unroll
        for (int z = 0; z < 16; z++) { kt[z] = 0.f; vt[z] = 0.f; }
        const float4* A = (const float4*)att + (t * NH + h) * 64;
        const float4* M = (const float4*)msg + (t * NH + h) * 64;
#pragma unroll
        for (int i = 0; i < 16; i++) {
            float ki = kreg[i], vi = vreg[i];
#pragma unroll
            for (int jc = 0; jc < 4; jc++) {
                float4 a = A[i * 4 + jc];
                kt[jc * 4 + 0] += ki * a.x; kt[jc * 4 + 1] += ki * a.y;
                kt[jc * 4 + 2] += ki * a.z; kt[jc * 4 + 3] += ki * a.w;
                float4 mm = M[i * 4 + jc];
                vt[jc * 4 + 0] += vi * mm.x; vt[jc * 4 + 1] += vi * mm.y;
                vt[jc * 4 + 2] += vi * mm.z; vt[jc * 4 + 3] += vi * mm.w;
            }
        }
        float pv = pri[t * NH + h] * 0.25f;   // fold pri*scale into kt
        __align__(16) __half2 hk[8], hv[8];
#pragma unroll
        for (int c = 0; c < 8; c++) {
            hk[c] = __floats2half2_rn(kt[2 * c] * pv, kt[2 * c + 1] * pv);
            hv[c] = __floats2half2_rn(vt[2 * c], vt[2 * c + 1]);
        }
        size_t off = ((size_t)(t * NH + h) * N_NODES + node) * DK;
        *((uint4*)&g_kt_h[off])     = *((uint4*)&hk[0]);
        *((uint4*)&g_kt_h[off + 8]) = *((uint4*)&hk[4]);
        *((uint4*)&g_vt_h[off])     = *((uint4*)&hv[0]);
        *((uint4*)&g_vt_h[off + 8]) = *((uint4*)&hv[4]);
    }
}

// ---------------- edge attention logits + deterministic running max ----------------
__global__ void k_logits() {
    int p = blockIdx.x * blockDim.x + threadIdx.x;
    int h = blockIdx.y;
    if (p >= N_EDGES) return;
    int eidx = g_eidx[p];                 // et*(NH*N) + src
    int d = g_dst_s[p];
    const __half2* kt = (const __half2*)(g_kt_h + ((size_t)eidx + (size_t)h * N_NODES) * DK);
    const float2*  qq = (const float2*)(g_kqv + (1 * NH + h) * (N_NODES * DK) + d * DK);
    float acc = 0.f;
#pragma unroll
    for (int c = 0; c < 8; c++) {
        float2 a = __half22float2(kt[c]);
        float2 b = qq[c];
        acc += a.x * b.x + a.y * b.y;
    }
    g_elog[(size_t)h * N_EDGES + p] = acc;
    atomicMax(&g_mkey[d * NH + h], fkey(acc));   // order-independent -> deterministic
}

// ---------------- edge softmax + aggregation (exp once; 4 edges in flight) ----------------
__global__ void k_agg() {
    int d = blockIdx.x;
    int h = threadIdx.x >> 5;
    int lane = threadIdx.x & 31;
    int rs = g_rowstart[d];
    int deg = g_rowstart[d + 1] - rs;
    int j2 = lane & 7, quad = lane >> 3;
    float* el = g_elog + (size_t)h * N_EDGES + rs;

    if (deg == 0) {
        if (lane < 8) ((float2*)&g_agg[d * DHID + h * DK])[j2] = make_float2(0.f, 0.f);
        return;
    }
    float m = fdec(g_mkey[d * NH + h]);
    // pass 1: exp once (cache into elog) + denom
    float s = 0.f;
    for (int i = lane; i < deg; i += 32) {
        float v = __expf(el[i] - m);
        el[i] = v;
        s += v;
    }
#pragma unroll
    for (int o = 16; o > 0; o >>= 1) s += __shfl_xor_sync(0xffffffffu, s, o);
    float inv = 1.f / s;
    // pass 2: weighted sum of fp16 vt (4 edges in flight; each lane covers 2 j's)
    float ax = 0.f, ay = 0.f;
    for (int i = quad; i < deg; i += 4) {
        float a = el[i];
        int eidx = g_eidx[rs + i];
        __half2 v = *((const __half2*)(g_vt_h + ((size_t)eidx + (size_t)h * N_NODES) * DK) + j2);
        float2 vf = __half22float2(v);
        ax += a * vf.x; ay += a * vf.y;
    }
#pragma unroll
    for (int o = 16; o >= 8; o >>= 1) {
        ax += __shfl_xor_sync(0xffffffffu, ax, o);
        ay += __shfl_xor_sync(0xffffffffu, ay, o);
    }
    if (lane < 8) ((float2*)&g_agg[d * DHID + h * DK])[j2] = make_float2(ax * inv, ay * inv);
}

// ---------------- output: relu(agg @ Wa[t] + x @ loop + bias) ----------------
__global__ void k_out(const float* __restrict__ x, const float* __restrict__ loopw,
                      const float* __restrict__ bias, float* __restrict__ out) {
    int t = blockIdx.y;
    int cnt = g_tstart[t + 1] - g_tstart[t];
    int tile = blockIdx.x * 64;
    if (tile >= cnt) return;

    __shared__ __align__(16) float xs[64][132];
    __shared__ __align__(16) float ws[16][128];
    __shared__ int rows[64];

    int tid = threadIdx.x;
    if (tid < 64) {
        int r = tile + tid;
        rows[tid] = (r < cnt) ? g_node_order[g_tstart[t] + r] : -1;
    }
    __syncthreads();

    int tc = tid & 31, tr = tid >> 5;
    float acc[8][4];
#pragma unroll
    for (int m = 0; m < 8; m++)
#pragma unroll
        for (int c = 0; c < 4; c++) acc[m][c] = 0.f;

    for (int ph = 0; ph < 2; ph++) {
        const float* A = (ph == 0) ? g_agg : x;
        const float* W = (ph == 0) ? (g_W + (3 * TN + t) * (DIN * DHID)) : loopw;
        __syncthreads();
        for (int i = tid; i < 64 * 32; i += 256) {
            int nr = i >> 5, c4 = i & 31;
            float4 v = make_float4(0.f, 0.f, 0.f, 0.f);
            int g = rows[nr];
            if (g >= 0) v = ((const float4*)A)[g * 32 + c4];
            *((float4*)&xs[nr][c4 * 4]) = v;
        }
        for (int kk = 0; kk < 8; kk++) {
            __syncthreads();
            for (int i = tid; i < 512; i += 256) {
                int r = i >> 5, c4 = i & 31;
                ((float4*)&ws[r][0])[c4] = ((const float4*)(W + (kk * 16 + r) * DHID))[c4];
            }
            __syncthreads();
#pragma unroll
            for (int k2 = 0; k2 < 16; k2++) {
                float4 b = *((const float4*)&ws[k2][tc * 4]);
#pragma unroll
                for (int m = 0; m < 8; m++) {
                    float a = xs[tr * 8 + m][kk * 16 + k2];
                    acc[m][0] += a * b.x; acc[m][1] += a * b.y;
                    acc[m][2] += a * b.z; acc[m][3] += a * b.w;
                }
            }
        }
    }

    float4 bv = *((const float4*)&bias[tc * 4]);
#pragma unroll
    for (int m = 0; m < 8; m++) {
        int g = rows[tr * 8 + m];
        if (g >= 0) {
            float4 o;
            o.x = fmaxf(acc[m][0] + bv.x, 0.f);
            o.y = fmaxf(acc[m][1] + bv.y, 0.f);
            o.z = fmaxf(acc[m][2] + bv.z, 0.f);
            o.w = fmaxf(acc[m][3] + bv.w, 0.f);
            *((float4*)&out[g * DHID + tc * 4]) = o;
        }
    }
}

// ---------------- launch ----------------
extern "C" void kernel_launch(void* const* d_in, const int* in_sizes, int n_in,
                              void* d_out, int out_size) {
    const float* x     = (const float*)d_in[0];
    const int*   ntype = (const int*)d_in[1];
    const int*   src   = (const int*)d_in[2];
    const int*   dst   = (const int*)d_in[3];
    const int*   etype = (const int*)d_in[4];
    const float* wck   = (const float*)d_in[5];
    const float* wbk   = (const float*)d_in[6];
    const float* wcq   = (const float*)d_in[7];
    const float* wbq   = (const float*)d_in[8];
    const float* wcv   = (const float*)d_in[9];
    const float* wbv   = (const float*)d_in[10];
    const float* wca   = (const float*)d_in[11];
    const float* wba   = (const float*)d_in[12];
    const float* pri   = (const float*)d_in[13];
    const float* att   = (const float*)d_in[14];
    const float* msg   = (const float*)d_in[15];
    const float* loopw = (const float*)d_in[16];
    const float* bias  = (const float*)d_in[17];
    float* out = (float*)d_out;

    k_init<<<(N_NODES * NH + 255) / 256, 256>>>();
    k_prepW<<<(4 * TN * DIN * DHID + 255) / 256, 256>>>(wck, wbk, wcq, wbq, wcv, wbv, wca, wba);
    k_count<<<(N_EDGES + 255) / 256, 256>>>(ntype, dst);
    k_scanA<<<NCHUNK, 1024>>>();
    k_scanB<<<1, 32>>>();
    k_scanC<<<NCHUNK, 1024>>>();
    k_scatter<<<(N_EDGES + 255) / 256, 256>>>(ntype, src, dst, etype);
    k_proj<<<dim3((N_NODES + 63) / 64, TN), 256>>>(x);
    k_relproj<<<(N_NODES + 31) / 32, 256>>>(att, msg, pri);
    k_logits<<<dim3((N_EDGES + 255) / 256, NH), 256>>>();
    k_agg<<<N_NODES, 256>>>();
    k_out<<<dim3((N_NODES + 63) / 64, TN), 256>>>(x, loopw, bias, out);
}